// round 15
// baseline (speedup 1.0000x reference)
#include <cuda_runtime.h>
#include <cuda_fp16.h>
#include <cstdint>
#include <cstddef>

#define NPTS 300000

static constexpr int kV0 = 60000, kV1 = 30000, kV2 = 15000, kV3 = 120000;
static constexpr int kTOTV = kV0 + kV1 + kV2 + kV3;            // 225000
static constexpr int kOFF0 = 0, kOFF1 = 60000, kOFF2 = 90000, kOFF3 = 105000;
static constexpr int kVIN = kV0 + kV1 + kV2;                   // 105000
static constexpr int kB = 2, kH = 512, kW = 512, kHW = kH * kW;
static constexpr int kSCB = (kTOTV + 1023) / 1024;             // 220 scan blocks

// ---------------- scratch (static device globals; no allocation) -------------
__device__ float4 g_sums[kTOTV];            // per-voxel point sums (x,y,z,w)
__device__ float  g_counts[kTOTV];          // per-voxel counts
__device__ int    g_offsets[kTOTV];         // per-scale exclusive scan of counts
__device__ int    g_rank[4 * NPTS];         // per-point rank within its voxel
__device__ int    g_blk[256];               // scan block totals
__device__ int    g_plist[4 * NPTS];        // CSR point lists, segmented per scale
__device__ __half g_sf1[(size_t)NPTS * 192];   // [N, 3*64] AVFE sf features (half)
__device__ __half g_vmax[(size_t)kVIN * 64];   // per-voxel max of sf, scales 0-2
__device__ __half g_sf2h[(size_t)NPTS * 128];  // [N,128] AVFEO sf, PERMUTED by plist3
__device__ __half g_wt[128 * 384];          // W_pt2 transposed to [n][k], half
__device__ float  g_omax[(size_t)kV3 * 128];   // per-voxel output max (coalesced)
__device__ int    g_occmap[kB * kHW];       // dense cell -> scale-3 voxel (-1 empty)

__device__ __forceinline__ float relu(float x) { return fmaxf(x, 0.f); }

__device__ __forceinline__ uint32_t smem_u32(const void* p) {
    uint32_t a;
    asm("{ .reg .u64 t; cvta.to.shared.u64 t, %1; cvt.u32.u64 %0, t; }"
        : "=r"(a) : "l"(p));
    return a;
}

__device__ __forceinline__ void cp_async16(uint32_t saddr, const void* gaddr,
                                           int src_bytes) {
    asm volatile("cp.async.cg.shared.global [%0], [%1], 16, %2;"
                 :: "r"(saddr), "l"(gaddr), "r"(src_bytes));
}
#define CP_COMMIT() asm volatile("cp.async.commit_group;" ::: "memory")
#define CP_WAIT(n)  asm volatile("cp.async.wait_group %0;" :: "n"(n) : "memory")

__device__ __forceinline__ void red_add_f4(float4* addr, float4 v) {
    asm volatile("red.global.add.v4.f32 [%0], {%1, %2, %3, %4};"
                 :: "l"(addr), "f"(v.x), "f"(v.y), "f"(v.z), "f"(v.w)
                 : "memory");
}

__device__ __forceinline__ void mma16816(float* c, uint32_t a0, uint32_t a1,
                                         uint32_t a2, uint32_t a3,
                                         uint32_t b0, uint32_t b1) {
    asm volatile(
        "mma.sync.aligned.m16n8k16.row.col.f32.f16.f16.f32 "
        "{%0,%1,%2,%3}, {%4,%5,%6,%7}, {%8,%9}, {%0,%1,%2,%3};"
        : "+f"(c[0]), "+f"(c[1]), "+f"(c[2]), "+f"(c[3])
        : "r"(a0), "r"(a1), "r"(a2), "r"(a3), "r"(b0), "r"(b1));
}

// ---------------- K0: zero scratch + occmap init + W_pt2 transpose ----------
__global__ void k_zero(const float* __restrict__ Wpt2) {
    int i = blockIdx.x * blockDim.x + threadIdx.x;
    if (i < kTOTV * 4) ((float*)g_sums)[i] = 0.f;
    if (i < kTOTV) g_counts[i] = 0.f;
    if (i < kB * kHW) g_occmap[i] = -1;
    if (i < 128 * 384) {
        int n = i / 384, k = i % 384;
        g_wt[i] = __float2half(Wpt2[k * 128 + n]);
    }
}
__global__ void k_occfill(const int* __restrict__ vfs) {
    int w = blockIdx.x * blockDim.x + threadIdx.x;
    if (w >= kV3) return;
    int vb = vfs[w * 3 + 0], vy = vfs[w * 3 + 1], vx = vfs[w * 3 + 2];
    g_occmap[vb * kHW + vy * kW + vx] = w;
}

// ------ K1: segment sums + counts (vector red.add) + per-point rank ---------
__global__ void k_accum(const float4* __restrict__ pts, const int* __restrict__ pvs) {
    int p = blockIdx.x * blockDim.x + threadIdx.x;
    if (p >= NPTS) return;
    float4 q = pts[p];
    const int off[4] = {kOFF0, kOFF1, kOFF2, kOFF3};
#pragma unroll
    for (int i = 0; i < 4; i++) {
        int b = off[i] + pvs[i * NPTS + p];
        red_add_f4(&g_sums[b], q);
        g_rank[i * NPTS + p] = (int)atomicAdd(&g_counts[b], 1.f);
    }
}

// ---------------- K2: global 3-phase exclusive scan of counts ---------------
__global__ __launch_bounds__(256) void k_scanA() {
    __shared__ int s[1024];
    __shared__ int warpsum[8];
    int b = blockIdx.x, tid = threadIdx.x;
    int base = b * 1024;
    for (int k = tid; k < 1024; k += 256) {
        int j = base + k;
        s[k] = (j < kTOTV) ? (int)g_counts[j] : 0;
    }
    __syncthreads();
    int e0 = s[4 * tid], e1 = s[4 * tid + 1], e2 = s[4 * tid + 2], e3 = s[4 * tid + 3];
    int tsum = e0 + e1 + e2 + e3;
    int lane = tid & 31, wid = tid >> 5;
    int x = tsum;
#pragma unroll
    for (int o = 1; o < 32; o <<= 1) {
        int y = __shfl_up_sync(~0u, x, o);
        if (lane >= o) x += y;
    }
    if (lane == 31) warpsum[wid] = x;
    __syncthreads();
    if (wid == 0) {
        int w = (lane < 8) ? warpsum[lane] : 0;
#pragma unroll
        for (int o = 1; o < 8; o <<= 1) {
            int y = __shfl_up_sync(~0u, w, o);
            if (lane >= o) w += y;
        }
        if (lane < 8) warpsum[lane] = w;   // inclusive warp totals
    }
    __syncthreads();
    int warpoff = (wid > 0) ? warpsum[wid - 1] : 0;
    int texcl = warpoff + x - tsum;        // exclusive prefix for this thread
    int j = base + 4 * tid;
    if (j < kTOTV)     g_offsets[j]     = texcl;
    texcl += e0;
    if (j + 1 < kTOTV) g_offsets[j + 1] = texcl;
    texcl += e1;
    if (j + 2 < kTOTV) g_offsets[j + 2] = texcl;
    texcl += e2;
    if (j + 3 < kTOTV) g_offsets[j + 3] = texcl;
    if (tid == 0) g_blk[b] = warpsum[7];
}

__global__ void k_scanB() {   // 1 block, 32 threads: exclusive scan of g_blk
    __shared__ int s[224];
    int tid = threadIdx.x;
    for (int k = tid; k < kSCB; k += 32) s[k] = g_blk[k];
    __syncwarp();
    int loc[7]; int sum = 0;
#pragma unroll
    for (int u = 0; u < 7; u++) {
        int k = tid * 7 + u;
        int v = (k < kSCB) ? s[k] : 0;
        loc[u] = sum; sum += v;
    }
    int x = sum;
#pragma unroll
    for (int o = 1; o < 32; o <<= 1) {
        int y = __shfl_up_sync(~0u, x, o);
        if (tid >= o) x += y;
    }
    int excl = x - sum;
#pragma unroll
    for (int u = 0; u < 7; u++) {
        int k = tid * 7 + u;
        if (k < kSCB) g_blk[k] = excl + loc[u];
    }
}

__global__ void k_scanC() {
    int j = blockIdx.x * 256 + threadIdx.x;
    if (j >= kTOTV) return;
    int sb;
    if (j < kOFF1)      sb = 0;
    else if (j < kOFF2) sb = NPTS;
    else if (j < kOFF3) sb = 2 * NPTS;
    else                sb = 3 * NPTS;
    g_offsets[j] += g_blk[j >> 10] - sb;
}

// ---------------- K3: fill CSR point lists (no atomics: use rank) -----------
__global__ void k_fill(const int* __restrict__ pvs) {
    int p = blockIdx.x * blockDim.x + threadIdx.x;
    if (p >= NPTS) return;
    const int off[4] = {kOFF0, kOFF1, kOFF2, kOFF3};
#pragma unroll
    for (int i = 0; i < 4; i++) {
        int b = off[i] + pvs[i * NPTS + p];
        g_plist[i * NPTS + g_offsets[b] + g_rank[i * NPTS + p]] = p;
    }
}

// ------ K4+K5 fused: AVFE compute + segment-max, voxel-major ----------------
__global__ __launch_bounds__(256) void k_avfemax(
    const float4* __restrict__ pts, const float* __restrict__ Wp1,
    const float* __restrict__ Wa1) {
    __shared__ float sWp[256];   // [4][64]
    __shared__ float sWa[512];   // [8][64]
    for (int j = threadIdx.x; j < 256; j += 256) sWp[j] = Wp1[j];
    for (int j = threadIdx.x; j < 512; j += 256) sWa[j] = Wa1[j];
    __syncthreads();

    int w = blockIdx.x * 8 + (threadIdx.x >> 5);
    if (w >= kVIN) return;
    int lane = threadIdx.x & 31;
    int c0 = lane, c1 = lane + 32;
    int i;
    if (w < kV0)            i = 0;
    else if (w < kV0 + kV1) i = 1;
    else                    i = 2;
    int b = w;                        // packed global voxel index
    int o = g_offsets[b];
    int cnt = (int)g_counts[b];
    const int* pl = &g_plist[i * NPTS + o];

    float inv = 1.0f / fmaxf((float)cnt, 1.0f);
    float4 s = g_sums[b];
    float m0v = s.x * inv, m1v = s.y * inv, m2v = s.z * inv, m3v = s.w * inv;
    float afc0 = m0v * sWa[256 + c0] + m1v * sWa[320 + c0] + m2v * sWa[384 + c0] + m3v * sWa[448 + c0];
    float afc1 = m0v * sWa[256 + c1] + m1v * sWa[320 + c1] + m2v * sWa[384 + c1] + m3v * sWa[448 + c1];

    float mx0 = 0.f, mx1 = 0.f;       // sf >= 0 always
    for (int t = 0; t < cnt; t++) {
        int p = pl[t];
        float4 q = pts[p];
        float pf0 = relu(q.x * sWp[c0] + q.y * sWp[64 + c0] + q.z * sWp[128 + c0] + q.w * sWp[192 + c0]);
        float pf1 = relu(q.x * sWp[c1] + q.y * sWp[64 + c1] + q.z * sWp[128 + c1] + q.w * sWp[192 + c1]);
        float a0 = q.x - m0v, a1 = q.y - m1v, a2 = q.z - m2v, a3 = q.w;
        float af0 = a0 * sWa[c0] + a1 * sWa[64 + c0] + a2 * sWa[128 + c0] + a3 * sWa[192 + c0] + afc0;
        float af1 = a0 * sWa[c1] + a1 * sWa[64 + c1] + a2 * sWa[128 + c1] + a3 * sWa[192 + c1] + afc1;
        float sf0 = pf0 * relu(af0);
        float sf1 = pf1 * relu(af1);
        size_t fb = (size_t)p * 192 + i * 64;
        g_sf1[fb + c0] = __float2half(sf0);
        g_sf1[fb + c1] = __float2half(sf1);
        mx0 = fmaxf(mx0, sf0);
        mx1 = fmaxf(mx1, sf1);
    }
    g_vmax[(size_t)b * 64 + lane]      = __float2half(mx0);
    g_vmax[(size_t)b * 64 + lane + 32] = __float2half(mx1);
}

// ------ K6: HMMA GEMM, rows PERMUTED by scale-3 CSR order -------------------
static constexpr int GSTRIDE = 40;

__global__ __launch_bounds__(256, 2) void k_gemm_mma(
    const float4* __restrict__ pts, const float* __restrict__ Watt2,
    const int* __restrict__ pvs) {
    __shared__ __align__(16) __half sA[2][128 * GSTRIDE];
    __shared__ __align__(16) __half sB[2][128 * GSTRIDE];
    __shared__ float sWs[1024];
    __shared__ int   svox[3][128];
    __shared__ int   splist[128];

    int tid = threadIdx.x;
    int warp = tid >> 5, lane = tid & 31;
    int p0 = blockIdx.x * 128;
    for (int j = tid; j < 1024; j += 256) sWs[j] = Watt2[j];
    if (tid < 128) {
        int jj = p0 + tid;
        splist[tid] = (jj < NPTS) ? g_plist[3 * NPTS + jj] : -1;
    }
    __syncthreads();   // splist needed below
    for (int j = tid; j < 384; j += 256) {
        int i = j >> 7, r = j & 127;
        int ps = splist[r];
        svox[i][r] = (ps >= 0) ? pvs[i * NPTS + ps] : 0;
    }
    __syncthreads();
    const int voff[3] = {kOFF0, kOFF1, kOFF2};

    float acc[16][4];
#pragma unroll
    for (int nt = 0; nt < 16; nt++)
#pragma unroll
        for (int j = 0; j < 4; j++) acc[nt][j] = 0.f;

    int row0 = tid >> 2, row1 = (256 + tid) >> 2;
    int seg = tid & 3;
    uint32_t sa_base = smem_u32(sA), sb_base = smem_u32(sB);
    const int BUFB = 128 * GSTRIDE * 2;   // bytes per buffer stage

    auto issue_chunk = [&](int c, int buf) {
        int i_s = c >> 2, sub = c & 3;
#pragma unroll
        for (int it = 0; it < 2; it++) {
            int row = it ? row1 : row0;
            int ps = splist[row];
            uint32_t sa = sa_base + buf * BUFB + (uint32_t)(row * GSTRIDE + seg * 8) * 2;
            const void* gsrc;
            int bytes = 16;
            if (sub < 2) {
                gsrc = &g_sf1[(size_t)(ps < 0 ? 0 : ps) * 192 + i_s * 64 + sub * 32 + seg * 8];
                if (ps < 0) bytes = 0;
            } else {
                int vox = svox[i_s][row];
                gsrc = &g_vmax[((size_t)(voff[i_s] + vox)) * 64 + (sub - 2) * 32 + seg * 8];
            }
            cp_async16(sa, gsrc, bytes);
            uint32_t sb = sb_base + buf * BUFB + (uint32_t)(row * GSTRIDE + seg * 8) * 2;
            cp_async16(sb, &g_wt[row * 384 + c * 32 + seg * 8], 16);
        }
        CP_COMMIT();
    };

    issue_chunk(0, 0);
    for (int c = 0; c < 12; c++) {
        int buf = c & 1;
        if (c < 11) issue_chunk(c + 1, buf ^ 1);
        if (c < 11) { CP_WAIT(1); } else { CP_WAIT(0); }
        __syncthreads();
        const __half* cA = sA[buf];
        const __half* cB = sB[buf];
#pragma unroll
        for (int ks = 0; ks < 2; ks++) {
            int ar = warp * 16 + (lane >> 2);
            int ac = ks * 16 + 2 * (lane & 3);
            uint32_t a0 = *(const uint32_t*)&cA[ar * GSTRIDE + ac];
            uint32_t a1 = *(const uint32_t*)&cA[(ar + 8) * GSTRIDE + ac];
            uint32_t a2 = *(const uint32_t*)&cA[ar * GSTRIDE + ac + 8];
            uint32_t a3 = *(const uint32_t*)&cA[(ar + 8) * GSTRIDE + ac + 8];
#pragma unroll
            for (int nt = 0; nt < 16; nt++) {
                int br = nt * 8 + (lane >> 2);
                int bc = ks * 16 + 2 * (lane & 3);
                uint32_t b0 = *(const uint32_t*)&cB[br * GSTRIDE + bc];
                uint32_t b1 = *(const uint32_t*)&cB[br * GSTRIDE + bc + 8];
                mma16816(acc[nt], a0, a1, a2, a3, b0, b1);
            }
        }
        __syncthreads();
    }

    // Epilogue: attention-2 + relu + half2 sf2 write at PERMUTED row j
    int rowa = warp * 16 + (lane >> 2);
#pragma unroll
    for (int rsel = 0; rsel < 2; rsel++) {
        int row = rowa + rsel * 8;
        int j = p0 + row;
        if (j >= NPTS) continue;
        int p = splist[row];
        int b = kOFF3 + pvs[3 * NPTS + p];
        float inv = 1.0f / fmaxf(g_counts[b], 1.0f);
        float4 s = g_sums[b];
        float4 q = pts[p];
        float m0 = s.x * inv, m1 = s.y * inv, m2 = s.z * inv, m3 = s.w * inv;
        float a0 = q.x - m0, a1 = q.y - m1, a2 = q.z - m2, a3 = q.w;
#pragma unroll
        for (int nt = 0; nt < 16; nt++) {
            int c = nt * 8 + 2 * (lane & 3);
            float af0 = a0 * sWs[c] + a1 * sWs[128 + c] + a2 * sWs[256 + c]
                      + a3 * sWs[384 + c] + m0 * sWs[512 + c] + m1 * sWs[640 + c]
                      + m2 * sWs[768 + c] + m3 * sWs[896 + c];
            int c1 = c + 1;
            float af1 = a0 * sWs[c1] + a1 * sWs[128 + c1] + a2 * sWs[256 + c1]
                      + a3 * sWs[384 + c1] + m0 * sWs[512 + c1] + m1 * sWs[640 + c1]
                      + m2 * sWs[768 + c1] + m3 * sWs[896 + c1];
            float v0 = relu(acc[nt][rsel * 2 + 0]) * relu(af0);
            float v1 = relu(acc[nt][rsel * 2 + 1]) * relu(af1);
            *(__half2*)&g_sf2h[(size_t)j * 128 + c] = __floats2half2_rn(v0, v1);
        }
    }
}

// ------ K7: streaming segment-max over permuted sf2 -> g_omax ---------------
__global__ __launch_bounds__(256) void k_vmax3() {
    int w = blockIdx.x * 8 + (threadIdx.x >> 5);
    if (w >= kV3) return;
    int lane = threadIdx.x & 31;
    int b = kOFF3 + w;
    int o = g_offsets[b];
    int cnt = (int)g_counts[b];
    float m0 = 0.f, m1 = 0.f, m2 = 0.f, m3 = 0.f;
    const __half* base = &g_sf2h[(size_t)o * 128];
    for (int t = 0; t < cnt; t++) {
        const __half* row = base + (size_t)t * 128;
        m0 = fmaxf(m0, __half2float(row[lane]));
        m1 = fmaxf(m1, __half2float(row[lane + 32]));
        m2 = fmaxf(m2, __half2float(row[lane + 64]));
        m3 = fmaxf(m3, __half2float(row[lane + 96]));
    }
    size_t ob = (size_t)w * 128;
    g_omax[ob + lane]      = m0;
    g_omax[ob + lane + 32] = m1;
    g_omax[ob + lane + 64] = m2;
    g_omax[ob + lane + 96] = m3;
}

// ------ K8: dense output writer, one (b,y) row per block --------------------
static constexpr int DCAP = 200;
static constexpr int DSM_BYTES = 512 * 4 + DCAP * 4 + 16 + DCAP * 129 * 4;

__global__ __launch_bounds__(256) void k_dense(float* __restrict__ out) {
    extern __shared__ char dsm[];
    int*   s_sidx = (int*)dsm;                       // [512]
    int*   s_vox  = (int*)(dsm + 2048);              // [DCAP]
    int*   s_cnt  = (int*)(dsm + 2048 + DCAP * 4);   // [1]
    float* s_om   = (float*)(dsm + 2048 + DCAP * 4 + 16); // [DCAP*129]

    int row = blockIdx.x;            // 0..kB*kH-1
    int b = row >> 9, y = row & 511;
    int tid = threadIdx.x;
    if (tid == 0) *s_cnt = 0;
    __syncthreads();

    int cellbase = b * kHW + y * kW;
    for (int x = tid; x < 512; x += 256) {
        int v = g_occmap[cellbase + x];
        int code = -1;
        if (v >= 0) {
            int slot = atomicAdd(s_cnt, 1);
            if (slot < DCAP) { s_vox[slot] = v; code = slot; }
            else             { code = -2 - v; }   // overflow: direct gather
        }
        s_sidx[x] = code;
    }
    __syncthreads();
    int cnt = min(*s_cnt, DCAP);
    for (int j = tid; j < cnt * 128; j += 256) {
        int slot = j >> 7, c = j & 127;
        s_om[slot * 129 + c] = g_omax[(size_t)s_vox[slot] * 128 + c];
    }
    __syncthreads();

    size_t outbase = ((size_t)b * 128) * kHW + (size_t)y * kW;
#pragma unroll 4
    for (int c = 0; c < 128; c++) {
        size_t ob = outbase + (size_t)c * kHW;
        for (int x = tid; x < 512; x += 256) {
            int code = s_sidx[x];
            float val = 0.f;
            if (code >= 0)       val = s_om[code * 129 + c];
            else if (code <= -2) val = g_omax[(size_t)(-2 - code) * 128 + c];
            out[ob + x] = val;
        }
    }
}

// ---------------------------------------------------------------------------
extern "C" void kernel_launch(void* const* d_in, const int* in_sizes, int n_in,
                              void* d_out, int out_size) {
    const float4* pts   = (const float4*)d_in[0];
    const float*  Wp1   = (const float*)d_in[1];
    const float*  Wa1   = (const float*)d_in[2];
    const float*  Wpt2  = (const float*)d_in[3];
    const float*  Watt2 = (const float*)d_in[4];
    const int*    pvs   = (const int*)d_in[5];
    const int*    vfs   = (const int*)d_in[6];
    float*        out   = (float*)d_out;

    cudaFuncSetAttribute(k_dense, cudaFuncAttributeMaxDynamicSharedMemorySize,
                         DSM_BYTES);

    k_zero<<<(kTOTV * 4 + 255) / 256, 256>>>(Wpt2);
    k_occfill<<<(kV3 + 255) / 256, 256>>>(vfs);
    k_accum<<<(NPTS + 255) / 256, 256>>>(pts, pvs);
    k_scanA<<<kSCB, 256>>>();
    k_scanB<<<1, 32>>>();
    k_scanC<<<(kTOTV + 255) / 256, 256>>>();
    k_fill<<<(NPTS + 255) / 256, 256>>>(pvs);
    k_avfemax<<<(kVIN + 7) / 8, 256>>>(pts, Wp1, Wa1);
    k_gemm_mma<<<(NPTS + 127) / 128, 256>>>(pts, Watt2, pvs);
    k_vmax3<<<(kV3 + 7) / 8, 256>>>();
    k_dense<<<kB * kH, 256, DSM_BYTES>>>(out);
}

// round 17
// speedup vs baseline: 1.4372x; 1.4372x over previous
#include <cuda_runtime.h>
#include <cuda_fp16.h>
#include <cstdint>
#include <cstddef>

#define NPTS 300000

static constexpr int kV0 = 60000, kV1 = 30000, kV2 = 15000, kV3 = 120000;
static constexpr int kTOTV = kV0 + kV1 + kV2 + kV3;            // 225000
static constexpr int kOFF0 = 0, kOFF1 = 60000, kOFF2 = 90000, kOFF3 = 105000;
static constexpr int kVIN = kV0 + kV1 + kV2;                   // 105000
static constexpr int kB = 2, kH = 512, kW = 512, kHW = kH * kW;
static constexpr int kSCB = (kTOTV + 1023) / 1024;             // 220 scan blocks

// ---------------- scratch (static device globals; no allocation) -------------
__device__ float4 g_sums[kTOTV];            // per-voxel point sums (x,y,z,w)
__device__ float  g_counts[kTOTV];          // per-voxel counts
__device__ int    g_offsets[kTOTV];         // per-scale exclusive scan of counts
__device__ int    g_rank[4 * NPTS];         // per-point rank within its voxel
__device__ int    g_blk[256];               // scan block totals
__device__ int    g_plist[4 * NPTS];        // CSR point lists, segmented per scale
__device__ __half g_sf1[(size_t)NPTS * 192];   // [N, 3*64] AVFE sf features (half)
__device__ __half g_vmax[(size_t)kVIN * 64];   // per-voxel max of sf, scales 0-2
__device__ __half g_sf2h[(size_t)NPTS * 128];  // [N,128] AVFEO sf, PERMUTED by plist3
__device__ __half g_wt[128 * 384];          // W_pt2 transposed to [n][k], half
__device__ float  g_omax[(size_t)kV3 * 128];   // per-voxel output max (coalesced)
__device__ int    g_occmap[kB * kHW];       // dense cell -> scale-3 voxel (-1 empty)

__device__ __forceinline__ float relu(float x) { return fmaxf(x, 0.f); }

__device__ __forceinline__ uint32_t smem_u32(const void* p) {
    uint32_t a;
    asm("{ .reg .u64 t; cvta.to.shared.u64 t, %1; cvt.u32.u64 %0, t; }"
        : "=r"(a) : "l"(p));
    return a;
}

__device__ __forceinline__ void cp_async16(uint32_t saddr, const void* gaddr,
                                           int src_bytes) {
    asm volatile("cp.async.cg.shared.global [%0], [%1], 16, %2;"
                 :: "r"(saddr), "l"(gaddr), "r"(src_bytes));
}
#define CP_COMMIT() asm volatile("cp.async.commit_group;" ::: "memory")
#define CP_WAIT(n)  asm volatile("cp.async.wait_group %0;" :: "n"(n) : "memory")

__device__ __forceinline__ void red_add_f4(float4* addr, float4 v) {
    asm volatile("red.global.add.v4.f32 [%0], {%1, %2, %3, %4};"
                 :: "l"(addr), "f"(v.x), "f"(v.y), "f"(v.z), "f"(v.w)
                 : "memory");
}

__device__ __forceinline__ void mma16816(float* c, uint32_t a0, uint32_t a1,
                                         uint32_t a2, uint32_t a3,
                                         uint32_t b0, uint32_t b1) {
    asm volatile(
        "mma.sync.aligned.m16n8k16.row.col.f32.f16.f16.f32 "
        "{%0,%1,%2,%3}, {%4,%5,%6,%7}, {%8,%9}, {%0,%1,%2,%3};"
        : "+f"(c[0]), "+f"(c[1]), "+f"(c[2]), "+f"(c[3])
        : "r"(a0), "r"(a1), "r"(a2), "r"(a3), "r"(b0), "r"(b1));
}

// ---------------- K0: zero scratch + occmap init + W_pt2 transpose ----------
__global__ void k_zero(const float* __restrict__ Wpt2) {
    int i = blockIdx.x * blockDim.x + threadIdx.x;
    if (i < kTOTV * 4) ((float*)g_sums)[i] = 0.f;
    if (i < kTOTV) g_counts[i] = 0.f;
    if (i < kB * kHW) g_occmap[i] = -1;
    if (i < 128 * 384) {
        int n = i / 384, k = i % 384;
        g_wt[i] = __float2half(Wpt2[k * 128 + n]);
    }
}
__global__ void k_occfill(const int* __restrict__ vfs) {
    int w = blockIdx.x * blockDim.x + threadIdx.x;
    if (w >= kV3) return;
    int vb = vfs[w * 3 + 0], vy = vfs[w * 3 + 1], vx = vfs[w * 3 + 2];
    g_occmap[vb * kHW + vy * kW + vx] = w;
}

// ------ K1: segment sums + counts (vector red.add) + per-point rank ---------
__global__ void k_accum(const float4* __restrict__ pts, const int* __restrict__ pvs) {
    int p = blockIdx.x * blockDim.x + threadIdx.x;
    if (p >= NPTS) return;
    float4 q = pts[p];
    const int off[4] = {kOFF0, kOFF1, kOFF2, kOFF3};
#pragma unroll
    for (int i = 0; i < 4; i++) {
        int b = off[i] + pvs[i * NPTS + p];
        red_add_f4(&g_sums[b], q);
        g_rank[i * NPTS + p] = (int)atomicAdd(&g_counts[b], 1.f);
    }
}

// ---------------- K2: global 3-phase exclusive scan of counts ---------------
__global__ __launch_bounds__(256) void k_scanA() {
    __shared__ int s[1024];
    __shared__ int warpsum[8];
    int b = blockIdx.x, tid = threadIdx.x;
    int base = b * 1024;
    for (int k = tid; k < 1024; k += 256) {
        int j = base + k;
        s[k] = (j < kTOTV) ? (int)g_counts[j] : 0;
    }
    __syncthreads();
    int e0 = s[4 * tid], e1 = s[4 * tid + 1], e2 = s[4 * tid + 2], e3 = s[4 * tid + 3];
    int tsum = e0 + e1 + e2 + e3;
    int lane = tid & 31, wid = tid >> 5;
    int x = tsum;
#pragma unroll
    for (int o = 1; o < 32; o <<= 1) {
        int y = __shfl_up_sync(~0u, x, o);
        if (lane >= o) x += y;
    }
    if (lane == 31) warpsum[wid] = x;
    __syncthreads();
    if (wid == 0) {
        int w = (lane < 8) ? warpsum[lane] : 0;
#pragma unroll
        for (int o = 1; o < 8; o <<= 1) {
            int y = __shfl_up_sync(~0u, w, o);
            if (lane >= o) w += y;
        }
        if (lane < 8) warpsum[lane] = w;   // inclusive warp totals
    }
    __syncthreads();
    int warpoff = (wid > 0) ? warpsum[wid - 1] : 0;
    int texcl = warpoff + x - tsum;        // exclusive prefix for this thread
    int j = base + 4 * tid;
    if (j < kTOTV)     g_offsets[j]     = texcl;
    texcl += e0;
    if (j + 1 < kTOTV) g_offsets[j + 1] = texcl;
    texcl += e1;
    if (j + 2 < kTOTV) g_offsets[j + 2] = texcl;
    texcl += e2;
    if (j + 3 < kTOTV) g_offsets[j + 3] = texcl;
    if (tid == 0) g_blk[b] = warpsum[7];
}

__global__ void k_scanB() {   // 1 block, 32 threads: exclusive scan of g_blk
    __shared__ int s[224];
    int tid = threadIdx.x;
    for (int k = tid; k < kSCB; k += 32) s[k] = g_blk[k];
    __syncwarp();
    int loc[7]; int sum = 0;
#pragma unroll
    for (int u = 0; u < 7; u++) {
        int k = tid * 7 + u;
        int v = (k < kSCB) ? s[k] : 0;
        loc[u] = sum; sum += v;
    }
    int x = sum;
#pragma unroll
    for (int o = 1; o < 32; o <<= 1) {
        int y = __shfl_up_sync(~0u, x, o);
        if (tid >= o) x += y;
    }
    int excl = x - sum;
#pragma unroll
    for (int u = 0; u < 7; u++) {
        int k = tid * 7 + u;
        if (k < kSCB) g_blk[k] = excl + loc[u];
    }
}

__global__ void k_scanC() {
    int j = blockIdx.x * 256 + threadIdx.x;
    if (j >= kTOTV) return;
    int sb;
    if (j < kOFF1)      sb = 0;
    else if (j < kOFF2) sb = NPTS;
    else if (j < kOFF3) sb = 2 * NPTS;
    else                sb = 3 * NPTS;
    g_offsets[j] += g_blk[j >> 10] - sb;
}

// ---------------- K3: fill CSR point lists (no atomics: use rank) -----------
__global__ void k_fill(const int* __restrict__ pvs) {
    int p = blockIdx.x * blockDim.x + threadIdx.x;
    if (p >= NPTS) return;
    const int off[4] = {kOFF0, kOFF1, kOFF2, kOFF3};
#pragma unroll
    for (int i = 0; i < 4; i++) {
        int b = off[i] + pvs[i * NPTS + p];
        g_plist[i * NPTS + g_offsets[b] + g_rank[i * NPTS + p]] = p;
    }
}

// ------ K4+K5 fused: AVFE compute + segment-max, voxel-major ----------------
__global__ __launch_bounds__(256) void k_avfemax(
    const float4* __restrict__ pts, const float* __restrict__ Wp1,
    const float* __restrict__ Wa1) {
    __shared__ float sWp[256];   // [4][64]
    __shared__ float sWa[512];   // [8][64]
    for (int j = threadIdx.x; j < 256; j += 256) sWp[j] = Wp1[j];
    for (int j = threadIdx.x; j < 512; j += 256) sWa[j] = Wa1[j];
    __syncthreads();

    int w = blockIdx.x * 8 + (threadIdx.x >> 5);
    if (w >= kVIN) return;
    int lane = threadIdx.x & 31;
    int c0 = lane, c1 = lane + 32;
    int i;
    if (w < kV0)            i = 0;
    else if (w < kV0 + kV1) i = 1;
    else                    i = 2;
    int b = w;                        // packed global voxel index
    int o = g_offsets[b];
    int cnt = (int)g_counts[b];
    const int* pl = &g_plist[i * NPTS + o];

    float inv = 1.0f / fmaxf((float)cnt, 1.0f);
    float4 s = g_sums[b];
    float m0v = s.x * inv, m1v = s.y * inv, m2v = s.z * inv, m3v = s.w * inv;
    float afc0 = m0v * sWa[256 + c0] + m1v * sWa[320 + c0] + m2v * sWa[384 + c0] + m3v * sWa[448 + c0];
    float afc1 = m0v * sWa[256 + c1] + m1v * sWa[320 + c1] + m2v * sWa[384 + c1] + m3v * sWa[448 + c1];

    float mx0 = 0.f, mx1 = 0.f;       // sf >= 0 always
    for (int t = 0; t < cnt; t++) {
        int p = pl[t];
        float4 q = pts[p];
        float pf0 = relu(q.x * sWp[c0] + q.y * sWp[64 + c0] + q.z * sWp[128 + c0] + q.w * sWp[192 + c0]);
        float pf1 = relu(q.x * sWp[c1] + q.y * sWp[64 + c1] + q.z * sWp[128 + c1] + q.w * sWp[192 + c1]);
        float a0 = q.x - m0v, a1 = q.y - m1v, a2 = q.z - m2v, a3 = q.w;
        float af0 = a0 * sWa[c0] + a1 * sWa[64 + c0] + a2 * sWa[128 + c0] + a3 * sWa[192 + c0] + afc0;
        float af1 = a0 * sWa[c1] + a1 * sWa[64 + c1] + a2 * sWa[128 + c1] + a3 * sWa[192 + c1] + afc1;
        float sf0 = pf0 * relu(af0);
        float sf1 = pf1 * relu(af1);
        size_t fb = (size_t)p * 192 + i * 64;
        g_sf1[fb + c0] = __float2half(sf0);
        g_sf1[fb + c1] = __float2half(sf1);
        mx0 = fmaxf(mx0, sf0);
        mx1 = fmaxf(mx1, sf1);
    }
    g_vmax[(size_t)b * 64 + lane]      = __float2half(mx0);
    g_vmax[(size_t)b * 64 + lane + 32] = __float2half(mx1);
}

// ------ K6: HMMA GEMM, rows PERMUTED by scale-3 CSR order -------------------
static constexpr int GSTRIDE = 40;

__global__ __launch_bounds__(256) void k_gemm_mma(
    const float4* __restrict__ pts, const float* __restrict__ Watt2,
    const int* __restrict__ pvs) {
    __shared__ __align__(16) __half sA[2][128 * GSTRIDE];
    __shared__ __align__(16) __half sB[2][128 * GSTRIDE];
    __shared__ float sWs[1024];
    __shared__ int   svox[3][128];
    __shared__ int   splist[128];

    int tid = threadIdx.x;
    int warp = tid >> 5, lane = tid & 31;
    int p0 = blockIdx.x * 128;
    for (int j = tid; j < 1024; j += 256) sWs[j] = Watt2[j];
    if (tid < 128) {
        int jj = p0 + tid;
        splist[tid] = (jj < NPTS) ? g_plist[3 * NPTS + jj] : -1;
    }
    __syncthreads();   // splist needed below
    for (int j = tid; j < 384; j += 256) {
        int i = j >> 7, r = j & 127;
        int ps = splist[r];
        svox[i][r] = (ps >= 0) ? pvs[i * NPTS + ps] : 0;
    }
    __syncthreads();
    const int voff[3] = {kOFF0, kOFF1, kOFF2};

    float acc[16][4];
#pragma unroll
    for (int nt = 0; nt < 16; nt++)
#pragma unroll
        for (int j = 0; j < 4; j++) acc[nt][j] = 0.f;

    int row0 = tid >> 2, row1 = (256 + tid) >> 2;
    int seg = tid & 3;
    uint32_t sa_base = smem_u32(sA), sb_base = smem_u32(sB);
    const int BUFB = 128 * GSTRIDE * 2;   // bytes per buffer stage

    auto issue_chunk = [&](int c, int buf) {
        int i_s = c >> 2, sub = c & 3;
#pragma unroll
        for (int it = 0; it < 2; it++) {
            int row = it ? row1 : row0;
            int ps = splist[row];
            uint32_t sa = sa_base + buf * BUFB + (uint32_t)(row * GSTRIDE + seg * 8) * 2;
            const void* gsrc;
            int bytes = 16;
            if (sub < 2) {
                gsrc = &g_sf1[(size_t)(ps < 0 ? 0 : ps) * 192 + i_s * 64 + sub * 32 + seg * 8];
                if (ps < 0) bytes = 0;
            } else {
                int vox = svox[i_s][row];
                gsrc = &g_vmax[((size_t)(voff[i_s] + vox)) * 64 + (sub - 2) * 32 + seg * 8];
            }
            cp_async16(sa, gsrc, bytes);
            uint32_t sb = sb_base + buf * BUFB + (uint32_t)(row * GSTRIDE + seg * 8) * 2;
            cp_async16(sb, &g_wt[row * 384 + c * 32 + seg * 8], 16);
        }
        CP_COMMIT();
    };

    issue_chunk(0, 0);
    for (int c = 0; c < 12; c++) {
        int buf = c & 1;
        if (c < 11) issue_chunk(c + 1, buf ^ 1);
        if (c < 11) { CP_WAIT(1); } else { CP_WAIT(0); }
        __syncthreads();
        const __half* cA = sA[buf];
        const __half* cB = sB[buf];
#pragma unroll
        for (int ks = 0; ks < 2; ks++) {
            int ar = warp * 16 + (lane >> 2);
            int ac = ks * 16 + 2 * (lane & 3);
            uint32_t a0 = *(const uint32_t*)&cA[ar * GSTRIDE + ac];
            uint32_t a1 = *(const uint32_t*)&cA[(ar + 8) * GSTRIDE + ac];
            uint32_t a2 = *(const uint32_t*)&cA[ar * GSTRIDE + ac + 8];
            uint32_t a3 = *(const uint32_t*)&cA[(ar + 8) * GSTRIDE + ac + 8];
#pragma unroll
            for (int nt = 0; nt < 16; nt++) {
                int br = nt * 8 + (lane >> 2);
                int bc = ks * 16 + 2 * (lane & 3);
                uint32_t b0 = *(const uint32_t*)&cB[br * GSTRIDE + bc];
                uint32_t b1 = *(const uint32_t*)&cB[br * GSTRIDE + bc + 8];
                mma16816(acc[nt], a0, a1, a2, a3, b0, b1);
            }
        }
        __syncthreads();
    }

    // Epilogue: attention-2 + relu + half2 sf2 write at PERMUTED row j
    int rowa = warp * 16 + (lane >> 2);
#pragma unroll
    for (int rsel = 0; rsel < 2; rsel++) {
        int row = rowa + rsel * 8;
        int j = p0 + row;
        if (j >= NPTS) continue;
        int p = splist[row];
        int b = kOFF3 + pvs[3 * NPTS + p];
        float inv = 1.0f / fmaxf(g_counts[b], 1.0f);
        float4 s = g_sums[b];
        float4 q = pts[p];
        float m0 = s.x * inv, m1 = s.y * inv, m2 = s.z * inv, m3 = s.w * inv;
        float a0 = q.x - m0, a1 = q.y - m1, a2 = q.z - m2, a3 = q.w;
#pragma unroll
        for (int nt = 0; nt < 16; nt++) {
            int c = nt * 8 + 2 * (lane & 3);
            float af0 = a0 * sWs[c] + a1 * sWs[128 + c] + a2 * sWs[256 + c]
                      + a3 * sWs[384 + c] + m0 * sWs[512 + c] + m1 * sWs[640 + c]
                      + m2 * sWs[768 + c] + m3 * sWs[896 + c];
            int c1 = c + 1;
            float af1 = a0 * sWs[c1] + a1 * sWs[128 + c1] + a2 * sWs[256 + c1]
                      + a3 * sWs[384 + c1] + m0 * sWs[512 + c1] + m1 * sWs[640 + c1]
                      + m2 * sWs[768 + c1] + m3 * sWs[896 + c1];
            float v0 = relu(acc[nt][rsel * 2 + 0]) * relu(af0);
            float v1 = relu(acc[nt][rsel * 2 + 1]) * relu(af1);
            *(__half2*)&g_sf2h[(size_t)j * 128 + c] = __floats2half2_rn(v0, v1);
        }
    }
}

// ------ K7: streaming segment-max over permuted sf2 -> g_omax ---------------
__global__ __launch_bounds__(256) void k_vmax3() {
    int w = blockIdx.x * 8 + (threadIdx.x >> 5);
    if (w >= kV3) return;
    int lane = threadIdx.x & 31;
    int b = kOFF3 + w;
    int o = g_offsets[b];
    int cnt = (int)g_counts[b];
    float m0 = 0.f, m1 = 0.f, m2 = 0.f, m3 = 0.f;
    const __half* base = &g_sf2h[(size_t)o * 128];
    for (int t = 0; t < cnt; t++) {
        const __half* row = base + (size_t)t * 128;
        m0 = fmaxf(m0, __half2float(row[lane]));
        m1 = fmaxf(m1, __half2float(row[lane + 32]));
        m2 = fmaxf(m2, __half2float(row[lane + 64]));
        m3 = fmaxf(m3, __half2float(row[lane + 96]));
    }
    size_t ob = (size_t)w * 128;
    g_omax[ob + lane]      = m0;
    g_omax[ob + lane + 32] = m1;
    g_omax[ob + lane + 64] = m2;
    g_omax[ob + lane + 96] = m3;
}

// ------ K8: dense output writer, one (b,y) row per block --------------------
static constexpr int DCAP = 200;
static constexpr int DSM_BYTES = 512 * 4 + DCAP * 4 + 16 + DCAP * 129 * 4;

__global__ __launch_bounds__(256) void k_dense(float* __restrict__ out) {
    extern __shared__ char dsm[];
    int*   s_sidx = (int*)dsm;                       // [512]
    int*   s_vox  = (int*)(dsm + 2048);              // [DCAP]
    int*   s_cnt  = (int*)(dsm + 2048 + DCAP * 4);   // [1]
    float* s_om   = (float*)(dsm + 2048 + DCAP * 4 + 16); // [DCAP*129]

    int row = blockIdx.x;            // 0..kB*kH-1
    int b = row >> 9, y = row & 511;
    int tid = threadIdx.x;
    if (tid == 0) *s_cnt = 0;
    __syncthreads();

    int cellbase = b * kHW + y * kW;
    for (int x = tid; x < 512; x += 256) {
        int v = g_occmap[cellbase + x];
        int code = -1;
        if (v >= 0) {
            int slot = atomicAdd(s_cnt, 1);
            if (slot < DCAP) { s_vox[slot] = v; code = slot; }
            else             { code = -2 - v; }   // overflow: direct gather
        }
        s_sidx[x] = code;
    }
    __syncthreads();
    int cnt = min(*s_cnt, DCAP);
    for (int j = tid; j < cnt * 128; j += 256) {
        int slot = j >> 7, c = j & 127;
        s_om[slot * 129 + c] = g_omax[(size_t)s_vox[slot] * 128 + c];
    }
    __syncthreads();

    size_t outbase = ((size_t)b * 128) * kHW + (size_t)y * kW;
#pragma unroll 4
    for (int c = 0; c < 128; c++) {
        size_t ob = outbase + (size_t)c * kHW;
        for (int x = tid; x < 512; x += 256) {
            int code = s_sidx[x];
            float val = 0.f;
            if (code >= 0)       val = s_om[code * 129 + c];
            else if (code <= -2) val = g_omax[(size_t)(-2 - code) * 128 + c];
            out[ob + x] = val;
        }
    }
}

// ---------------------------------------------------------------------------
extern "C" void kernel_launch(void* const* d_in, const int* in_sizes, int n_in,
                              void* d_out, int out_size) {
    const float4* pts   = (const float4*)d_in[0];
    const float*  Wp1   = (const float*)d_in[1];
    const float*  Wa1   = (const float*)d_in[2];
    const float*  Wpt2  = (const float*)d_in[3];
    const float*  Watt2 = (const float*)d_in[4];
    const int*    pvs   = (const int*)d_in[5];
    const int*    vfs   = (const int*)d_in[6];
    float*        out   = (float*)d_out;

    cudaFuncSetAttribute(k_dense, cudaFuncAttributeMaxDynamicSharedMemorySize,
                         DSM_BYTES);

    k_zero<<<(kTOTV * 4 + 255) / 256, 256>>>(Wpt2);
    k_occfill<<<(kV3 + 255) / 256, 256>>>(vfs);
    k_accum<<<(NPTS + 255) / 256, 256>>>(pts, pvs);
    k_scanA<<<kSCB, 256>>>();
    k_scanB<<<1, 32>>>();
    k_scanC<<<(kTOTV + 255) / 256, 256>>>();
    k_fill<<<(NPTS + 255) / 256, 256>>>(pvs);
    k_avfemax<<<(kVIN + 7) / 8, 256>>>(pts, Wp1, Wa1);
    k_gemm_mma<<<(NPTS + 127) / 128, 256>>>(pts, Watt2, pvs);
    k_vmax3<<<(kV3 + 7) / 8, 256>>>();
    k_dense<<<kB * kH, 256, DSM_BYTES>>>(out);
}